// round 12
// baseline (speedup 1.0000x reference)
#include <cuda_runtime.h>
#include <cstdint>

#define B_ 4
#define N_ 2048
#define IND_ 256
#define H_ 4
#define D_ 64
#define HD_ 256
#define M_ (B_*N_)
#define NEG_SLOPE 0.2f
#define LOG2E 1.4426950408889634f

#define QTILE 128
#define JT 64
#define JSPLIT 4
#define JRANGE (N_/JSPLIT)          // 512 j per block
#define NCHB (JRANGE/JT)            // 8 chunks per block
#define NW (N_/32)                  // bitmask words per row = 64

// Scratch (static __device__ arrays; no allocation allowed)
__device__ float g_hT[B_*H_*D_*N_];    // [bh][d][n], 8 MB
__device__ float g_srcT[B_*H_*N_];     // [bh][n]
__device__ float g_dstT[B_*H_*N_];
__device__ unsigned g_bm[NW*N_];       // bit-packed mask TRANSPOSED [w][q]
__device__ float g_pmax[B_*H_*32];     // per-(bh, m-block) max dst (no atomics)
__device__ float g_pout[JSPLIT*B_*H_*N_*D_];   // 32 MB partial AV
__device__ float g_plsum[JSPLIT*B_*H_*N_];     // partial lsum
__device__ unsigned g_ticket[(N_/QTILE)*B_*H_]; // 256 split-k tickets

// ---------------------------------------------------------------------------
// helpers
// ---------------------------------------------------------------------------
__device__ __forceinline__ float ex2f(float x) {
    float r; asm("ex2.approx.f32 %0, %1;" : "=f"(r) : "f"(x)); return r;
}
__device__ __forceinline__ unsigned long long dupf(float v) {
    unsigned long long r;
    unsigned u = __float_as_uint(v);
    asm("mov.b64 %0, {%1, %1};" : "=l"(r) : "r"(u));
    return r;
}
#define FFMA2(d, a, b) asm("fma.rn.f32x2 %0, %1, %2, %0;" : "+l"(d) : "l"(a), "l"(b))

__device__ __forceinline__ uint32_t smem_u32(const void* p) {
    uint32_t a;
    asm("{ .reg .u64 tmp; cvta.to.shared.u64 tmp, %1; cvt.u32.u64 %0, tmp; }"
        : "=r"(a) : "l"(p));
    return a;
}
#define LDSM4(r0, r1, r2, r3, addr) \
    asm volatile("ldmatrix.sync.aligned.m8n8.x4.shared.b16 {%0,%1,%2,%3}, [%4];" \
                 : "=r"(r0), "=r"(r1), "=r"(r2), "=r"(r3) : "r"(addr))
#define MMA_TF32(d0, d1, d2, d3, a0, a1, a2, a3, b0, b1) \
    asm volatile("mma.sync.aligned.m16n8k8.row.col.f32.tf32.tf32.f32 " \
                 "{%0,%1,%2,%3}, {%4,%5,%6,%7}, {%8,%9}, {%0,%1,%2,%3};" \
                 : "+f"(d0), "+f"(d1), "+f"(d2), "+f"(d3) \
                 : "r"(a0), "r"(a1), "r"(a2), "r"(a3), "r"(b0), "r"(b1))
#define CP16(dst, src) \
    asm volatile("cp.async.ca.shared.global [%0], [%1], 16;" \
                 :: "r"(dst), "l"((const void*)(src)) : "memory")
#define CP4(dst, src) \
    asm volatile("cp.async.ca.shared.global [%0], [%1], 4;" \
                 :: "r"(dst), "l"((const void*)(src)) : "memory")
#define CP_COMMIT() asm volatile("cp.async.commit_group;" ::: "memory")
#define CP_WAIT(n)  asm volatile("cp.async.wait_group %0;" :: "n"(n) : "memory")

// ---------------------------------------------------------------------------
// Kernel 1: h = x @ W (FFMA2) + FUSED bitpack + transposed g_hT + src/dst +
// per-block dst max (plain stores, no atomics) + ticket reset.
// ---------------------------------------------------------------------------
__global__ __launch_bounds__(256) void k_gemm(const float* __restrict__ x,
                                              const float* __restrict__ W,
                                              const float* __restrict__ a_src,
                                              const float* __restrict__ a_dst,
                                              const int* __restrict__ A_mask) {
    __shared__ float As[16][68];
    __shared__ float Bs[16][68];
    __shared__ float redS[64][17];
    __shared__ float redD[64][17];
    __shared__ float wmx[2];
    const int t  = threadIdx.x;
    const int m0 = blockIdx.x * 64;
    const int n0 = blockIdx.y * 64;
    const int lb = blockIdx.y * (M_ / 64) + blockIdx.x;   // 0..511

    // ---- fused mask bitpack (covers all N_*NW words across the grid) ----
    {
        int tid = lb * 256 + t;
        int q = tid & (N_ - 1);
        int w2 = tid >> 11;
        const int4* p = (const int4*)(A_mask + q * N_ + w2 * 32);
        unsigned bits = 0;
        #pragma unroll
        for (int i = 0; i < 8; i++) {
            int4 m = p[i];
            bits |= (unsigned)(m.x != 0) << (4*i)
                 |  (unsigned)(m.y != 0) << (4*i+1)
                 |  (unsigned)(m.z != 0) << (4*i+2)
                 |  (unsigned)(m.w != 0) << (4*i+3);
        }
        g_bm[w2 * N_ + q] = bits;
    }
    if (lb == 0) g_ticket[t] = 0u;   // read by the NEXT kernel (stream order)

    const int tq = t >> 4, td = t & 15;
    const int am = t >> 2, ak4 = (t & 3) << 2;
    const int bk = t >> 4, bn4 = (t & 15) << 2;

    unsigned long long acc[4][2];
    #pragma unroll
    for (int i = 0; i < 4; i++) { acc[i][0] = 0ull; acc[i][1] = 0ull; }

    for (int k0 = 0; k0 < IND_; k0 += 16) {
        float4 av = *(const float4*)(x + (m0 + am) * IND_ + k0 + ak4);
        float4 bv = *(const float4*)(W + (k0 + bk) * HD_ + n0 + bn4);
        __syncthreads();
        As[ak4 + 0][am] = av.x;
        As[ak4 + 1][am] = av.y;
        As[ak4 + 2][am] = av.z;
        As[ak4 + 3][am] = av.w;
        *(float4*)&Bs[bk][bn4] = bv;
        __syncthreads();
        #pragma unroll
        for (int k = 0; k < 16; k++) {
            float a0[4];
            *(float4*)a0 = *(const float4*)&As[k][tq << 2];
            ulonglong2 bl = *(const ulonglong2*)&Bs[k][td << 2];
            #pragma unroll
            for (int i = 0; i < 4; i++) {
                unsigned long long ad = dupf(a0[i]);
                FFMA2(acc[i][0], ad, bl.x);
                FFMA2(acc[i][1], ad, bl.y);
            }
        }
    }
    float fm[4][4];
    #pragma unroll
    for (int i = 0; i < 4; i++) {
        unsigned lo, hi;
        asm("mov.b64 {%0, %1}, %2;" : "=r"(lo), "=r"(hi) : "l"(acc[i][0]));
        fm[i][0] = __uint_as_float(lo); fm[i][1] = __uint_as_float(hi);
        asm("mov.b64 {%0, %1}, %2;" : "=r"(lo), "=r"(hi) : "l"(acc[i][1]));
        fm[i][2] = __uint_as_float(lo); fm[i][3] = __uint_as_float(hi);
    }
    const int b  = m0 >> 11;
    const int nn = m0 & (N_ - 1);
    const int bh = b * H_ + (n0 >> 6);

    float* bp = g_hT + (bh * D_ + td * 4) * N_ + nn + tq * 4;
    #pragma unroll
    for (int dd = 0; dd < 4; dd++)
        *(float4*)(bp + dd * N_) = make_float4(fm[0][dd], fm[1][dd], fm[2][dd], fm[3][dd]);

    {
        float sa4[4], sd4[4];
        #pragma unroll
        for (int dd = 0; dd < 4; dd++) {
            sa4[dd] = a_src[n0 + td * 4 + dd];
            sd4[dd] = a_dst[n0 + td * 4 + dd];
        }
        #pragma unroll
        for (int i = 0; i < 4; i++) {
            float ps = 0.f, pd = 0.f;
            #pragma unroll
            for (int dd = 0; dd < 4; dd++) {
                ps = fmaf(fm[i][dd], sa4[dd], ps);
                pd = fmaf(fm[i][dd], sd4[dd], pd);
            }
            redS[tq * 4 + i][td] = ps;
            redD[tq * 4 + i][td] = pd;
        }
    }
    __syncthreads();
    if (t < 64) {
        float s = 0.f, d = 0.f;
        #pragma unroll
        for (int j = 0; j < 16; j++) { s += redS[t][j]; d += redD[t][j]; }
        g_srcT[bh * N_ + nn + t] = s;
        g_dstT[bh * N_ + nn + t] = d;
        float mm = d;
        #pragma unroll
        for (int o = 16; o; o >>= 1)
            mm = fmaxf(mm, __shfl_xor_sync(0xffffffffu, mm, o));
        if ((t & 31) == 0) wmx[t >> 5] = mm;
    }
    __syncthreads();
    if (t == 0) g_pmax[bh * 32 + (nn >> 6)] = fmaxf(wmx[0], wmx[1]);
}

// ---------------------------------------------------------------------------
// Kernel 2: attention partials on mma.sync tf32; 4 warps x 32 q-rows;
// cp.async double-buffered staging (no staging registers, latency hidden in
// group waits). Last-arriving split block combines, normalizes, ELUs, stores.
// ---------------------------------------------------------------------------
// smem float offsets
#define KT0_F   0                      // 64 x 68
#define KT1_F   4352
#define SDST_F  8704                   // 2 x 64
#define SBM_F   8832                   // 2 x 256 (unsigned)
#define SRC_F   9344                   // 128
#define CL_F    9472                   // 128
#define MD_F    9600                   // 1 (block max-dst)
#define SM_TOTF 9604                   // floats = 38416 B
#define KT_DB   17408                  // byte delta between Kt buffers

__global__ __launch_bounds__(128, 5) void k_attn(float* __restrict__ out) {
    extern __shared__ float sm[];
    float*    sDst = sm + SDST_F;
    unsigned* sBm  = (unsigned*)(sm + SBM_F);
    float*    sSrc = sm + SRC_F;
    float*    sCl  = sm + CL_F;

    const int t    = threadIdx.x;
    const int w    = t >> 5, lane = t & 31;
    const int qt0  = blockIdx.x * QTILE;
    const int bh   = blockIdx.y;
    const int jr   = blockIdx.z;
    const int jbase = jr * JRANGE;

    // per-row src + per-(bh) max-dst (reduce 32 per-block partial maxes)
    const float srow = g_srcT[bh * N_ + qt0 + t];
    sSrc[t] = srow;
    if (w == 0) {
        float v = g_pmax[bh * 32 + lane];
        #pragma unroll
        for (int o = 16; o; o >>= 1) v = fmaxf(v, __shfl_xor_sync(0xffffffffu, v, o));
        if (lane == 0) sm[MD_F] = v;
    }

    // ---- Kt staging: kd = t&63, 32 floats/thread via cp.async ----
    const int kd   = t & 63;
    const int kj   = (t >> 6) << 5;
    const float* ksrc0 = g_hT + (bh * D_ + kd) * N_ + kj + jbase;

    // ---- fragment lane mapping: warp owns q rows w*32..+31, frags f=0,1 ----
    const int g  = lane >> 2;
    const int lc = lane & 3;
    const int qr0 = w * 32 + g;
    const int qr1 = qr0 + 16;

    // ---- byte addresses ----
    const uint32_t smb = smem_u32(sm);
    const uint32_t kaddr0 = smb + (uint32_t)((KT0_F + kd * 68 + kj) << 2);
    const uint32_t kaddr1 = kaddr0 + KT_DB;
    const int lm = lane >> 3, lr = lane & 7;
    uint32_t baddr0[4];
    #pragma unroll
    for (int p = 0; p < 4; p++) {
        int nt = p + ((lm >> 1) << 2);
        baddr0[p] = smb + (uint32_t)((KT0_F + (nt * 8 + lr) * 68
                                      + ((lm & 1) << 2)) << 2);
    }

    __syncthreads();   // sSrc + sMd visible
    {
        float l = srow + sm[MD_F];
        float C = fmaxf(l, NEG_SLOPE * l);
        sCl[t] = C * LOG2E;
    }

#define STAGE(cnext, s)                                                       \
    {                                                                         \
        const float* ks = ksrc0 + (cnext) * JT;                               \
        uint32_t ka = (s) ? kaddr1 : kaddr0;                                  \
        _Pragma("unroll")                                                     \
        for (int i = 0; i < 8; i++)                                           \
            CP16(ka + i * 16, ks + i * 4);                                    \
        const int j0a = jbase + (cnext) * JT;                                 \
        if (t < JT) CP4(smb + ((SDST_F + (s) * 64 + t) << 2),                 \
                        g_dstT + bh * N_ + j0a + t);                          \
        CP4(smb + ((SBM_F + (s) * 256 + t) << 2),                             \
            g_bm + (j0a >> 5) * N_ + qt0 + t);                                \
        CP4(smb + ((SBM_F + (s) * 256 + 128 + t) << 2),                       \
            g_bm + ((j0a >> 5) + 1) * N_ + qt0 + t);                          \
    }

    STAGE(0, 0);
    CP_COMMIT();
    __syncthreads();   // sCl visible
    const float sva0 = sSrc[qr0],     Cla0 = sCl[qr0];
    const float svb0 = sSrc[qr0 + 8], Clb0 = sCl[qr0 + 8];
    const float sva1 = sSrc[qr1],     Cla1 = sCl[qr1];
    const float svb1 = sSrc[qr1 + 8], Clb1 = sCl[qr1 + 8];

    float acc[2][8][4];
    #pragma unroll
    for (int f = 0; f < 2; f++)
        #pragma unroll
        for (int n = 0; n < 8; n++)
            #pragma unroll
            for (int i = 0; i < 4; i++) acc[f][n][i] = 0.f;
    float lsA0 = 0.f, lsB0 = 0.f, lsA1 = 0.f, lsB1 = 0.f;

    for (int ch = 0; ch < NCHB; ch++) {
        const int sel = ch & 1;
        __syncthreads();                 // all reads of buffer sel^1 finished
        if (ch < NCHB - 1) {
            if (sel) STAGE(ch + 1, 0)
            else     STAGE(ch + 1, 1)
            CP_COMMIT();
            CP_WAIT(1);                  // buffer sel's group complete
        } else {
            CP_WAIT(0);
        }
        __syncthreads();                 // buffer sel visible to all

        const float*    sD = sDst + sel * 64;
        const unsigned* sB = sBm + sel * 256;
        const unsigned long long bmA0 =
            ((((unsigned long long)sB[128 + qr0] << 32) | sB[qr0]) >> lc);
        const unsigned long long bmB0 =
            ((((unsigned long long)sB[128 + qr0 + 8] << 32) | sB[qr0 + 8]) >> lc);
        const unsigned long long bmA1 =
            ((((unsigned long long)sB[128 + qr1] << 32) | sB[qr1]) >> lc);
        const unsigned long long bmB1 =
            ((((unsigned long long)sB[128 + qr1 + 8] << 32) | sB[qr1 + 8]) >> lc);
        const uint32_t bdlt = (uint32_t)(sel * KT_DB);

        #pragma unroll
        for (int k = 0; k < 8; k++) {
            const int j1 = (k << 3) + lc;
            const int j2 = j1 + 4;
            float d1 = sD[j1], d2 = sD[j2];
            // frag 0
            float l0 = sva0 + d1, l1 = svb0 + d1, l2 = sva0 + d2, l3 = svb0 + d2;
            l0 = fmaxf(l0, NEG_SLOPE * l0);
            l1 = fmaxf(l1, NEG_SLOPE * l1);
            l2 = fmaxf(l2, NEG_SLOPE * l2);
            l3 = fmaxf(l3, NEG_SLOPE * l3);
            float e0 = ex2f(fmaf(l0, LOG2E, -Cla0));
            float e1 = ex2f(fmaf(l1, LOG2E, -Clb0));
            float e2 = ex2f(fmaf(l2, LOG2E, -Cla0));
            float e3 = ex2f(fmaf(l3, LOG2E, -Clb0));
            e0 = ((bmA0 >> (k << 3)) & 1ull) ? e0 : 0.f;
            e1 = ((bmB0 >> (k << 3)) & 1ull) ? e1 : 0.f;
            e2 = ((bmA0 >> ((k << 3) + 4)) & 1ull) ? e2 : 0.f;
            e3 = ((bmB0 >> ((k << 3) + 4)) & 1ull) ? e3 : 0.f;
            lsA0 += e0 + e2; lsB0 += e1 + e3;
            // frag 1
            float m0 = sva1 + d1, m1 = svb1 + d1, m2 = sva1 + d2, m3 = svb1 + d2;
            m0 = fmaxf(m0, NEG_SLOPE * m0);
            m1 = fmaxf(m1, NEG_SLOPE * m1);
            m2 = fmaxf(m2, NEG_SLOPE * m2);
            m3 = fmaxf(m3, NEG_SLOPE * m3);
            float f0 = ex2f(fmaf(m0, LOG2E, -Cla1));
            float f1 = ex2f(fmaf(m1, LOG2E, -Clb1));
            float f2 = ex2f(fmaf(m2, LOG2E, -Cla1));
            float f3 = ex2f(fmaf(m3, LOG2E, -Clb1));
            f0 = ((bmA1 >> (k << 3)) & 1ull) ? f0 : 0.f;
            f1 = ((bmB1 >> (k << 3)) & 1ull) ? f1 : 0.f;
            f2 = ((bmA1 >> ((k << 3) + 4)) & 1ull) ? f2 : 0.f;
            f3 = ((bmB1 >> ((k << 3) + 4)) & 1ull) ? f3 : 0.f;
            lsA1 += f0 + f2; lsB1 += f1 + f3;

            const uint32_t a0 = __float_as_uint(e0), a1 = __float_as_uint(e1);
            const uint32_t a2 = __float_as_uint(e2), a3 = __float_as_uint(e3);
            const uint32_t c0 = __float_as_uint(f0), c1 = __float_as_uint(f1);
            const uint32_t c2 = __float_as_uint(f2), c3 = __float_as_uint(f3);
            #pragma unroll
            for (int p = 0; p < 4; p++) {
                uint32_t b0, b1, b2, b3;
                LDSM4(b0, b1, b2, b3, baddr0[p] + bdlt + (k << 5));
                MMA_TF32(acc[0][p][0], acc[0][p][1], acc[0][p][2], acc[0][p][3],
                         a0, a1, a2, a3, b0, b1);
                MMA_TF32(acc[0][p+4][0], acc[0][p+4][1], acc[0][p+4][2], acc[0][p+4][3],
                         a0, a1, a2, a3, b2, b3);
                MMA_TF32(acc[1][p][0], acc[1][p][1], acc[1][p][2], acc[1][p][3],
                         c0, c1, c2, c3, b0, b1);
                MMA_TF32(acc[1][p+4][0], acc[1][p+4][1], acc[1][p+4][2], acc[1][p+4][3],
                         c0, c1, c2, c3, b2, b3);
            }
        }
    }
#undef STAGE

    // ---- lsum reduce over lc quad; write partial sums ----
    lsA0 += __shfl_xor_sync(0xffffffffu, lsA0, 1);
    lsA0 += __shfl_xor_sync(0xffffffffu, lsA0, 2);
    lsB0 += __shfl_xor_sync(0xffffffffu, lsB0, 1);
    lsB0 += __shfl_xor_sync(0xffffffffu, lsB0, 2);
    lsA1 += __shfl_xor_sync(0xffffffffu, lsA1, 1);
    lsA1 += __shfl_xor_sync(0xffffffffu, lsA1, 2);
    lsB1 += __shfl_xor_sync(0xffffffffu, lsB1, 1);
    lsB1 += __shfl_xor_sync(0xffffffffu, lsB1, 2);
    const int ngbase = (jr * (B_ * H_) + bh) * N_ + qt0;
    if (lc == 0) {
        g_plsum[ngbase + qr0]      = lsA0;
        g_plsum[ngbase + qr0 + 8]  = lsB0;
        g_plsum[ngbase + qr1]      = lsA1;
        g_plsum[ngbase + qr1 + 8]  = lsB1;
    }

    // ---- write unnormalized partial AV ----
    #pragma unroll
    for (int f = 0; f < 2; f++) {
        const int ra = (f ? qr1 : qr0);
        float* pa = g_pout + (size_t)(ngbase + ra) * D_ + lc * 2;
        float* pb = g_pout + (size_t)(ngbase + ra + 8) * D_ + lc * 2;
        #pragma unroll
        for (int nt = 0; nt < 8; nt++) {
            *(float2*)(pa + nt * 8) = make_float2(acc[f][nt][0], acc[f][nt][1]);
            *(float2*)(pb + nt * 8) = make_float2(acc[f][nt][2], acc[f][nt][3]);
        }
    }

    // ---- split-k combine: last-arriving block of this (qtile,bh) ----
    __threadfence();
    __syncthreads();
    __shared__ unsigned s_last;
    if (t == 0) {
        unsigned old = atomicAdd(&g_ticket[blockIdx.x * (B_ * H_) + bh], 1u);
        s_last = (old == JSPLIT - 1) ? 1u : 0u;
    }
    __syncthreads();
    if (s_last) {
        const int d4  = t & 15;
        const int qb0 = t >> 4;
        const int b2  = bh >> 2, hh2 = bh & 3;
        #pragma unroll
        for (int pass = 0; pass < 16; pass++) {
            const int q  = qb0 + pass * 8;
            const int ng = bh * N_ + qt0 + q;
            float ls = 0.f;
            float4 s4 = make_float4(0.f, 0.f, 0.f, 0.f);
            #pragma unroll
            for (int p = 0; p < JSPLIT; p++) {
                const int pg = p * (B_ * H_) * N_ + ng;
                ls += g_plsum[pg];
                float4 v = *(const float4*)(g_pout + (size_t)pg * D_ + d4 * 4);
                s4.x += v.x; s4.y += v.y; s4.z += v.z; s4.w += v.w;
            }
            const float inv = 1.f / ls;
            float v0 = s4.x * inv, v1 = s4.y * inv, v2 = s4.z * inv, v3 = s4.w * inv;
            v0 = (v0 > 0.f) ? v0 : expm1f(v0);
            v1 = (v1 > 0.f) ? v1 : expm1f(v1);
            v2 = (v2 > 0.f) ? v2 : expm1f(v2);
            v3 = (v3 > 0.f) ? v3 : expm1f(v3);
            *(float4*)(out + (size_t)(b2 * N_ + qt0 + q) * HD_ + hh2 * D_ + d4 * 4) =
                make_float4(v0, v1, v2, v3);
        }
    }
}

// ---------------------------------------------------------------------------
extern "C" void kernel_launch(void* const* d_in, const int* in_sizes, int n_in,
                              void* d_out, int out_size) {
    const float* x      = (const float*)d_in[0];
    const int*   A_mask = (const int*)d_in[1];
    const float* W      = (const float*)d_in[2];
    const float* a_src  = (const float*)d_in[3];
    const float* a_dst  = (const float*)d_in[4];
    float* out = (float*)d_out;

    cudaFuncSetAttribute(k_attn, cudaFuncAttributeMaxDynamicSharedMemorySize,
                         SM_TOTF * (int)sizeof(float));

    k_gemm<<<dim3(M_ / 64, HD_ / 64), 256>>>(x, W, a_src, a_dst, A_mask);
    k_attn<<<dim3(N_ / QTILE, B_ * H_, JSPLIT), 128,
             SM_TOTF * (int)sizeof(float)>>>(out);
}

// round 13
// speedup vs baseline: 1.2804x; 1.2804x over previous
#include <cuda_runtime.h>
#include <cstdint>

#define B_ 4
#define N_ 2048
#define IND_ 256
#define H_ 4
#define D_ 64
#define HD_ 256
#define M_ (B_*N_)
#define NEG_SLOPE 0.2f
#define LOG2E 1.4426950408889634f

#define QTILE 128
#define JT 64
#define JSPLIT 4
#define JRANGE (N_/JSPLIT)          // 512 j per block
#define NCHB (JRANGE/JT)            // 8 chunks per block
#define NW (N_/32)                  // bitmask words per row = 64

// Scratch (static __device__ arrays; no allocation allowed)
__device__ float g_hT[B_*H_*D_*N_];    // [bh][d][n], 8 MB
__device__ float g_srcT[B_*H_*N_];     // [bh][n]
__device__ float g_dstT[B_*H_*N_];
__device__ unsigned g_bm[NW*N_];       // bit-packed mask TRANSPOSED [w][q]
__device__ float g_pmax[B_*H_*32];     // per-(bh, m-block) max dst (no atomics)
__device__ float g_pout[JSPLIT*B_*H_*N_*D_];   // 32 MB partial AV
__device__ float g_plsum[JSPLIT*B_*H_*N_];     // partial lsum
__device__ unsigned g_ticket[(N_/QTILE)*B_*H_]; // 256 split-k tickets

// ---------------------------------------------------------------------------
// helpers
// ---------------------------------------------------------------------------
__device__ __forceinline__ float ex2f(float x) {
    float r; asm("ex2.approx.f32 %0, %1;" : "=f"(r) : "f"(x)); return r;
}
__device__ __forceinline__ unsigned long long dupf(float v) {
    unsigned long long r;
    unsigned u = __float_as_uint(v);
    asm("mov.b64 %0, {%1, %1};" : "=l"(r) : "r"(u));
    return r;
}
#define FFMA2(d, a, b) asm("fma.rn.f32x2 %0, %1, %2, %0;" : "+l"(d) : "l"(a), "l"(b))

__device__ __forceinline__ uint32_t smem_u32(const void* p) {
    uint32_t a;
    asm("{ .reg .u64 tmp; cvta.to.shared.u64 tmp, %1; cvt.u32.u64 %0, tmp; }"
        : "=r"(a) : "l"(p));
    return a;
}
#define LDSM4(r0, r1, r2, r3, addr) \
    asm volatile("ldmatrix.sync.aligned.m8n8.x4.shared.b16 {%0,%1,%2,%3}, [%4];" \
                 : "=r"(r0), "=r"(r1), "=r"(r2), "=r"(r3) : "r"(addr))
#define MMA_TF32(d0, d1, d2, d3, a0, a1, a2, a3, b0, b1) \
    asm volatile("mma.sync.aligned.m16n8k8.row.col.f32.tf32.tf32.f32 " \
                 "{%0,%1,%2,%3}, {%4,%5,%6,%7}, {%8,%9}, {%0,%1,%2,%3};" \
                 : "+f"(d0), "+f"(d1), "+f"(d2), "+f"(d3) \
                 : "r"(a0), "r"(a1), "r"(a2), "r"(a3), "r"(b0), "r"(b1))

// ---------------------------------------------------------------------------
// Kernel 1: h = x @ W (FFMA2) + FUSED bitpack + transposed g_hT + src/dst +
// per-block dst max (plain stores, no atomics) + ticket reset.
// ---------------------------------------------------------------------------
__global__ __launch_bounds__(256) void k_gemm(const float* __restrict__ x,
                                              const float* __restrict__ W,
                                              const float* __restrict__ a_src,
                                              const float* __restrict__ a_dst,
                                              const int* __restrict__ A_mask) {
    __shared__ float As[16][68];
    __shared__ float Bs[16][68];
    __shared__ float redS[64][17];
    __shared__ float redD[64][17];
    __shared__ float wmx[2];
    const int t  = threadIdx.x;
    const int m0 = blockIdx.x * 64;
    const int n0 = blockIdx.y * 64;
    const int lb = blockIdx.y * (M_ / 64) + blockIdx.x;   // 0..511

    // ---- fused mask bitpack (grid covers all N_*NW words) ----
    {
        int tid = lb * 256 + t;
        int q = tid & (N_ - 1);
        int w2 = tid >> 11;
        const int4* p = (const int4*)(A_mask + q * N_ + w2 * 32);
        unsigned bits = 0;
        #pragma unroll
        for (int i = 0; i < 8; i++) {
            int4 m = p[i];
            bits |= (unsigned)(m.x != 0) << (4*i)
                 |  (unsigned)(m.y != 0) << (4*i+1)
                 |  (unsigned)(m.z != 0) << (4*i+2)
                 |  (unsigned)(m.w != 0) << (4*i+3);
        }
        g_bm[w2 * N_ + q] = bits;
    }
    if (lb == 0) g_ticket[t] = 0u;   // read by the NEXT kernel (stream order)

    const int tq = t >> 4, td = t & 15;
    const int am = t >> 2, ak4 = (t & 3) << 2;
    const int bk = t >> 4, bn4 = (t & 15) << 2;

    unsigned long long acc[4][2];
    #pragma unroll
    for (int i = 0; i < 4; i++) { acc[i][0] = 0ull; acc[i][1] = 0ull; }

    for (int k0 = 0; k0 < IND_; k0 += 16) {
        float4 av = *(const float4*)(x + (m0 + am) * IND_ + k0 + ak4);
        float4 bv = *(const float4*)(W + (k0 + bk) * HD_ + n0 + bn4);
        __syncthreads();
        As[ak4 + 0][am] = av.x;
        As[ak4 + 1][am] = av.y;
        As[ak4 + 2][am] = av.z;
        As[ak4 + 3][am] = av.w;
        *(float4*)&Bs[bk][bn4] = bv;
        __syncthreads();
        #pragma unroll
        for (int k = 0; k < 16; k++) {
            float a0[4];
            *(float4*)a0 = *(const float4*)&As[k][tq << 2];
            ulonglong2 bl = *(const ulonglong2*)&Bs[k][td << 2];
            #pragma unroll
            for (int i = 0; i < 4; i++) {
                unsigned long long ad = dupf(a0[i]);
                FFMA2(acc[i][0], ad, bl.x);
                FFMA2(acc[i][1], ad, bl.y);
            }
        }
    }
    float fm[4][4];
    #pragma unroll
    for (int i = 0; i < 4; i++) {
        unsigned lo, hi;
        asm("mov.b64 {%0, %1}, %2;" : "=r"(lo), "=r"(hi) : "l"(acc[i][0]));
        fm[i][0] = __uint_as_float(lo); fm[i][1] = __uint_as_float(hi);
        asm("mov.b64 {%0, %1}, %2;" : "=r"(lo), "=r"(hi) : "l"(acc[i][1]));
        fm[i][2] = __uint_as_float(lo); fm[i][3] = __uint_as_float(hi);
    }
    const int b  = m0 >> 11;
    const int nn = m0 & (N_ - 1);
    const int bh = b * H_ + (n0 >> 6);

    float* bp = g_hT + (bh * D_ + td * 4) * N_ + nn + tq * 4;
    #pragma unroll
    for (int dd = 0; dd < 4; dd++)
        *(float4*)(bp + dd * N_) = make_float4(fm[0][dd], fm[1][dd], fm[2][dd], fm[3][dd]);

    {
        float sa4[4], sd4[4];
        #pragma unroll
        for (int dd = 0; dd < 4; dd++) {
            sa4[dd] = a_src[n0 + td * 4 + dd];
            sd4[dd] = a_dst[n0 + td * 4 + dd];
        }
        #pragma unroll
        for (int i = 0; i < 4; i++) {
            float ps = 0.f, pd = 0.f;
            #pragma unroll
            for (int dd = 0; dd < 4; dd++) {
                ps = fmaf(fm[i][dd], sa4[dd], ps);
                pd = fmaf(fm[i][dd], sd4[dd], pd);
            }
            redS[tq * 4 + i][td] = ps;
            redD[tq * 4 + i][td] = pd;
        }
    }
    __syncthreads();
    if (t < 64) {
        float s = 0.f, d = 0.f;
        #pragma unroll
        for (int j = 0; j < 16; j++) { s += redS[t][j]; d += redD[t][j]; }
        g_srcT[bh * N_ + nn + t] = s;
        g_dstT[bh * N_ + nn + t] = d;
        float mm = d;
        #pragma unroll
        for (int o = 16; o; o >>= 1)
            mm = fmaxf(mm, __shfl_xor_sync(0xffffffffu, mm, o));
        if ((t & 31) == 0) wmx[t >> 5] = mm;
    }
    __syncthreads();
    if (t == 0) g_pmax[bh * 32 + (nn >> 6)] = fmaxf(wmx[0], wmx[1]);
}

// ---------------------------------------------------------------------------
// Kernel 2: attention partials, mma.sync tf32; 4 warps x 32 q-rows; REGISTER
// staging (R11 structure, one barrier per chunk). Last-arriving split block
// combines, normalizes, ELUs, stores.
// ---------------------------------------------------------------------------
// smem float offsets
#define KT0_F   0                      // 64 x 68
#define KT1_F   4352
#define SDST_F  8704                   // 2 x 64
#define SBM_F   8832                   // 2 x 256 (unsigned)
#define SRC_F   9344                   // 128
#define CL_F    9472                   // 128
#define MD_F    9600                   // 1 (block max-dst)
#define SM_TOTF 9604                   // floats = 38416 B
#define KT_DB   17408                  // byte delta between Kt buffers

__global__ __launch_bounds__(128, 4) void k_attn(float* __restrict__ out) {
    extern __shared__ float sm[];
    float*    sDst = sm + SDST_F;
    unsigned* sBm  = (unsigned*)(sm + SBM_F);
    float*    sSrc = sm + SRC_F;
    float*    sCl  = sm + CL_F;

    const int t    = threadIdx.x;
    const int w    = t >> 5, lane = t & 31;
    const int qt0  = blockIdx.x * QTILE;
    const int bh   = blockIdx.y;
    const int jr   = blockIdx.z;
    const int jbase = jr * JRANGE;

    // per-row src + per-(bh) max-dst (reduce 32 per-block partial maxes)
    const float srow = g_srcT[bh * N_ + qt0 + t];
    sSrc[t] = srow;
    if (w == 0) {
        float v = g_pmax[bh * 32 + lane];
        #pragma unroll
        for (int o = 16; o; o >>= 1) v = fmaxf(v, __shfl_xor_sync(0xffffffffu, v, o));
        if (lane == 0) sm[MD_F] = v;
    }
    __syncthreads();     // MD_F + sSrc visible
    {
        float l = srow + sm[MD_F];
        float C = fmaxf(l, NEG_SLOPE * l);
        sCl[t] = C * LOG2E;
    }

    // ---- Kt staging: kd = t&63 (conflict-free STS.128), 32 floats/thread ----
    const int kd   = t & 63;
    const int kj   = (t >> 6) << 5;
    const int krow_off = kd * 68 + kj;
    const float* ksrc0 = g_hT + (bh * D_ + kd) * N_ + kj + jbase;

    // ---- fragment lane mapping: warp owns q rows w*32..+31, frags f=0,1 ----
    const int g  = lane >> 2;
    const int lc = lane & 3;
    const int qr0 = w * 32 + g;
    const int qr1 = qr0 + 16;

    // ---- ldmatrix B lane addresses (byte, buffer 0) ----
    const uint32_t smb = smem_u32(sm);
    const int lm = lane >> 3, lr = lane & 7;
    uint32_t baddr0[4];
    #pragma unroll
    for (int p = 0; p < 4; p++) {
        int nt = p + ((lm >> 1) << 2);
        baddr0[p] = smb + (uint32_t)((KT0_F + (nt * 8 + lr) * 68
                                      + ((lm & 1) << 2)) << 2);
    }

    __syncthreads();     // sCl visible
    const float sva0 = sSrc[qr0],     Cla0 = sCl[qr0];
    const float svb0 = sSrc[qr0 + 8], Clb0 = sCl[qr0 + 8];
    const float sva1 = sSrc[qr1],     Cla1 = sCl[qr1];
    const float svb1 = sSrc[qr1 + 8], Clb1 = sCl[qr1 + 8];

    float acc[2][8][4];
    #pragma unroll
    for (int f = 0; f < 2; f++)
        #pragma unroll
        for (int n = 0; n < 8; n++)
            #pragma unroll
            for (int i = 0; i < 4; i++) acc[f][n][i] = 0.f;
    float lsA0 = 0.f, lsB0 = 0.f, lsA1 = 0.f, lsB1 = 0.f;

#define STAGE(j0, s)                                                          \
    {                                                                         \
        float* krow = sm + ((s) ? KT1_F : KT0_F) + krow_off;                  \
        const float* ks = ksrc0 + ((j0) - jbase);                             \
        _Pragma("unroll")                                                     \
        for (int i = 0; i < 8; i++)                                           \
            *(float4*)(krow + (i << 2)) = *(const float4*)(ks + (i << 2));    \
        if (t < JT) sDst[(s) * 64 + t] = g_dstT[bh * N_ + (j0) + t];          \
        sBm[(s) * 256 + t]       = g_bm[((j0) >> 5) * N_ + qt0 + t];          \
        sBm[(s) * 256 + 128 + t] = g_bm[(((j0) >> 5) + 1) * N_ + qt0 + t];    \
    }

    STAGE(jbase, 0);

    for (int ch = 0; ch < NCHB; ch++) {
        const int sel = ch & 1;
        __syncthreads();
        if (ch < NCHB - 1) {
            if (sel) STAGE(jbase + (ch + 1) * JT, 0)
            else     STAGE(jbase + (ch + 1) * JT, 1)
        }
        const float*    sD = sDst + sel * 64;
        const unsigned* sB = sBm + sel * 256;
        const unsigned long long bmA0 =
            ((((unsigned long long)sB[128 + qr0] << 32) | sB[qr0]) >> lc);
        const unsigned long long bmB0 =
            ((((unsigned long long)sB[128 + qr0 + 8] << 32) | sB[qr0 + 8]) >> lc);
        const unsigned long long bmA1 =
            ((((unsigned long long)sB[128 + qr1] << 32) | sB[qr1]) >> lc);
        const unsigned long long bmB1 =
            ((((unsigned long long)sB[128 + qr1 + 8] << 32) | sB[qr1 + 8]) >> lc);
        const uint32_t bdlt = (uint32_t)(sel * KT_DB);

        #pragma unroll
        for (int k = 0; k < 8; k++) {
            const int j1 = (k << 3) + lc;
            const int j2 = j1 + 4;
            float d1 = sD[j1], d2 = sD[j2];
            // frag 0
            float l0 = sva0 + d1, l1 = svb0 + d1, l2 = sva0 + d2, l3 = svb0 + d2;
            l0 = fmaxf(l0, NEG_SLOPE * l0);
            l1 = fmaxf(l1, NEG_SLOPE * l1);
            l2 = fmaxf(l2, NEG_SLOPE * l2);
            l3 = fmaxf(l3, NEG_SLOPE * l3);
            float e0 = ex2f(fmaf(l0, LOG2E, -Cla0));
            float e1 = ex2f(fmaf(l1, LOG2E, -Clb0));
            float e2 = ex2f(fmaf(l2, LOG2E, -Cla0));
            float e3 = ex2f(fmaf(l3, LOG2E, -Clb0));
            e0 = ((bmA0 >> (k << 3)) & 1ull) ? e0 : 0.f;
            e1 = ((bmB0 >> (k << 3)) & 1ull) ? e1 : 0.f;
            e2 = ((bmA0 >> ((k << 3) + 4)) & 1ull) ? e2 : 0.f;
            e3 = ((bmB0 >> ((k << 3) + 4)) & 1ull) ? e3 : 0.f;
            lsA0 += e0 + e2; lsB0 += e1 + e3;
            // frag 1
            float m0 = sva1 + d1, m1 = svb1 + d1, m2 = sva1 + d2, m3 = svb1 + d2;
            m0 = fmaxf(m0, NEG_SLOPE * m0);
            m1 = fmaxf(m1, NEG_SLOPE * m1);
            m2 = fmaxf(m2, NEG_SLOPE * m2);
            m3 = fmaxf(m3, NEG_SLOPE * m3);
            float f0 = ex2f(fmaf(m0, LOG2E, -Cla1));
            float f1 = ex2f(fmaf(m1, LOG2E, -Clb1));
            float f2 = ex2f(fmaf(m2, LOG2E, -Cla1));
            float f3 = ex2f(fmaf(m3, LOG2E, -Clb1));
            f0 = ((bmA1 >> (k << 3)) & 1ull) ? f0 : 0.f;
            f1 = ((bmB1 >> (k << 3)) & 1ull) ? f1 : 0.f;
            f2 = ((bmA1 >> ((k << 3) + 4)) & 1ull) ? f2 : 0.f;
            f3 = ((bmB1 >> ((k << 3) + 4)) & 1ull) ? f3 : 0.f;
            lsA1 += f0 + f2; lsB1 += f1 + f3;

            const uint32_t a0 = __float_as_uint(e0), a1 = __float_as_uint(e1);
            const uint32_t a2 = __float_as_uint(e2), a3 = __float_as_uint(e3);
            const uint32_t c0 = __float_as_uint(f0), c1 = __float_as_uint(f1);
            const uint32_t c2 = __float_as_uint(f2), c3 = __float_as_uint(f3);
            #pragma unroll
            for (int p = 0; p < 4; p++) {
                uint32_t b0, b1, b2, b3;
                LDSM4(b0, b1, b2, b3, baddr0[p] + bdlt + (k << 5));
                MMA_TF32(acc[0][p][0], acc[0][p][1], acc[0][p][2], acc[0][p][3],
                         a0, a1, a2, a3, b0, b1);
                MMA_TF32(acc[0][p+4][0], acc[0][p+4][1], acc[0][p+4][2], acc[0][p+4][3],
                         a0, a1, a2, a3, b2, b3);
                MMA_TF32(acc[1][p][0], acc[1][p][1], acc[1][p][2], acc[1][p][3],
                         c0, c1, c2, c3, b0, b1);
                MMA_TF32(acc[1][p+4][0], acc[1][p+4][1], acc[1][p+4][2], acc[1][p+4][3],
                         c0, c1, c2, c3, b2, b3);
            }
        }
    }
#undef STAGE

    // ---- lsum reduce over lc quad; write partial sums ----
    lsA0 += __shfl_xor_sync(0xffffffffu, lsA0, 1);
    lsA0 += __shfl_xor_sync(0xffffffffu, lsA0, 2);
    lsB0 += __shfl_xor_sync(0xffffffffu, lsB0, 1);
    lsB0 += __shfl_xor_sync(0xffffffffu, lsB0, 2);
    lsA1 += __shfl_xor_sync(0xffffffffu, lsA1, 1);
    lsA1 += __shfl_xor_sync(0xffffffffu, lsA1, 2);
    lsB1 += __shfl_xor_sync(0xffffffffu, lsB1, 1);
    lsB1 += __shfl_xor_sync(0xffffffffu, lsB1, 2);
    const int ngbase = (jr * (B_ * H_) + bh) * N_ + qt0;
    if (lc == 0) {
        g_plsum[ngbase + qr0]      = lsA0;
        g_plsum[ngbase + qr0 + 8]  = lsB0;
        g_plsum[ngbase + qr1]      = lsA1;
        g_plsum[ngbase + qr1 + 8]  = lsB1;
    }

    // ---- write unnormalized partial AV ----
    #pragma unroll
    for (int f = 0; f < 2; f++) {
        const int ra = (f ? qr1 : qr0);
        float* pa = g_pout + (size_t)(ngbase + ra) * D_ + lc * 2;
        float* pb = g_pout + (size_t)(ngbase + ra + 8) * D_ + lc * 2;
        #pragma unroll
        for (int nt = 0; nt < 8; nt++) {
            *(float2*)(pa + nt * 8) = make_float2(acc[f][nt][0], acc[f][nt][1]);
            *(float2*)(pb + nt * 8) = make_float2(acc[f][nt][2], acc[f][nt][3]);
        }
    }

    // ---- split-k combine: last-arriving block of this (qtile,bh) ----
    __threadfence();
    __syncthreads();
    __shared__ unsigned s_last;
    if (t == 0) {
        unsigned old = atomicAdd(&g_ticket[blockIdx.x * (B_ * H_) + bh], 1u);
        s_last = (old == JSPLIT - 1) ? 1u : 0u;
    }
    __syncthreads();
    if (s_last) {
        const int d4  = t & 15;
        const int qb0 = t >> 4;
        const int b2  = bh >> 2, hh2 = bh & 3;
        #pragma unroll
        for (int pass = 0; pass < 16; pass++) {
            const int q  = qb0 + pass * 8;
            const int ng = bh * N_ + qt0 + q;
            float ls = 0.f;
            float4 s4 = make_float4(0.f, 0.f, 0.f, 0.f);
            #pragma unroll
            for (int p = 0; p < JSPLIT; p++) {
                const int pg = p * (B_ * H_) * N_ + ng;
                ls += g_plsum[pg];
                float4 v = *(const float4*)(g_pout + (size_t)pg * D_ + d4 * 4);
                s4.x += v.x; s4.y += v.y; s4.z += v.z; s4.w += v.w;
            }
            const float inv = 1.f / ls;
            float v0 = s4.x * inv, v1 = s4.y * inv, v2 = s4.z * inv, v3 = s4.w * inv;
            v0 = (v0 > 0.f) ? v0 : expm1f(v0);
            v1 = (v1 > 0.f) ? v1 : expm1f(v1);
            v2 = (v2 > 0.f) ? v2 : expm1f(v2);
            v3 = (v3 > 0.f) ? v3 : expm1f(v3);
            *(float4*)(out + (size_t)(b2 * N_ + qt0 + q) * HD_ + hh2 * D_ + d4 * 4) =
                make_float4(v0, v1, v2, v3);
        }
    }
}

// ---------------------------------------------------------------------------
extern "C" void kernel_launch(void* const* d_in, const int* in_sizes, int n_in,
                              void* d_out, int out_size) {
    const float* x      = (const float*)d_in[0];
    const int*   A_mask = (const int*)d_in[1];
    const float* W      = (const float*)d_in[2];
    const float* a_src  = (const float*)d_in[3];
    const float* a_dst  = (const float*)d_in[4];
    float* out = (float*)d_out;

    cudaFuncSetAttribute(k_attn, cudaFuncAttributeMaxDynamicSharedMemorySize,
                         SM_TOTF * (int)sizeof(float));

    k_gemm<<<dim3(M_ / 64, HD_ / 64), 256>>>(x, W, a_src, a_dst, A_mask);
    k_attn<<<dim3(N_ / QTILE, B_ * H_, JSPLIT), 128,
             SM_TOTF * (int)sizeof(float)>>>(out);
}